// round 3
// baseline (speedup 1.0000x reference)
#include <cuda_runtime.h>
#include <cuda_bf16.h>

#define MAXN 50000
#define MAXE 1000000
#define C 64

// ---------------- device scratch (no allocations allowed) ----------------
__device__ __align__(16) float d_tmp[MAXN * C];   // pre-agg h (x@W); reused as A in MLP stage
__device__ __align__(16) float d_h[MAXN * C];     // layer output (relu'd)
__device__ __align__(16) float d_B[MAXN * C];     // h@Wm1_bot
__device__ float d_al[MAXN];
__device__ float d_ar[MAXN];
__device__ int   d_cnt[MAXN];
__device__ int   d_cur[MAXN];
__device__ int   d_rp[MAXN + 1];
__device__ int   d_csr[MAXE];

// ---------------- CSR build ----------------
__global__ void zero_k(int n) {
    int i = blockIdx.x * blockDim.x + threadIdx.x;
    if (i < n) d_cnt[i] = 0;
}

__global__ void count_k(const int* __restrict__ ei, int E) {
    int e = blockIdx.x * blockDim.x + threadIdx.x;
    if (e < E) atomicAdd(&d_cnt[ei[E + e]], 1);
}

// single-block scan over up to MAXN counts
__global__ void scan_k(int n) {
    __shared__ int warpsum[32];
    __shared__ int s_carry;
    int tid = threadIdx.x, lane = tid & 31, w = tid >> 5;
    if (tid == 0) s_carry = 0;
    __syncthreads();
    for (int base = 0; base < n; base += 1024) {
        int i = base + tid;
        int v = (i < n) ? d_cnt[i] : 0;
        int x = v;
        #pragma unroll
        for (int o = 1; o < 32; o <<= 1) {
            int t = __shfl_up_sync(~0u, x, o);
            if (lane >= o) x += t;
        }
        if (lane == 31) warpsum[w] = x;
        __syncthreads();
        if (w == 0) {
            int y = warpsum[lane];
            #pragma unroll
            for (int o = 1; o < 32; o <<= 1) {
                int t = __shfl_up_sync(~0u, y, o);
                if (lane >= o) y += t;
            }
            warpsum[lane] = y;
        }
        __syncthreads();
        int incl = x + (w > 0 ? warpsum[w - 1] : 0) + s_carry;
        if (i < n) { d_rp[i] = incl - v; d_cur[i] = incl - v; }
        __syncthreads();
        if (tid == 1023) s_carry = incl;
        __syncthreads();
    }
    if (threadIdx.x == 0) d_rp[n] = s_carry;
}

__global__ void scatter_k(const int* __restrict__ ei, int E) {
    int e = blockIdx.x * blockDim.x + threadIdx.x;
    if (e < E) {
        int src = ei[e];
        int dst = ei[E + e];
        int pos = atomicAdd(&d_cur[dst], 1);
        d_csr[pos] = src;
    }
}

// ---------------- GEMM bodies (Y fixed to scratch symbols) ----------------
__device__ __forceinline__ void gemm64_body(const float* __restrict__ X,
                                            const float* __restrict__ W,
                                            float* __restrict__ Y, int n) {
    __shared__ float sW[64 * 64];
    __shared__ float sX[16 * 64];
    int tid = threadIdx.x;  // 256
    int row0 = blockIdx.x * 16;
    #pragma unroll
    for (int i = 0; i < 16; i++) sW[tid + 256 * i] = W[tid + 256 * i];
    #pragma unroll
    for (int i = 0; i < 4; i++) {
        int idx = tid + 256 * i;
        int r = idx >> 6, c = idx & 63;
        int gr = row0 + r;
        sX[idx] = (gr < n) ? X[gr * 64 + c] : 0.f;
    }
    __syncthreads();
    int r = tid >> 4;
    int c4 = (tid & 15) * 4;
    float4 acc = {0.f, 0.f, 0.f, 0.f};
    #pragma unroll
    for (int k = 0; k < 64; k++) {
        float xv = sX[r * 64 + k];
        float4 w4 = *(const float4*)&sW[k * 64 + c4];
        acc.x += xv * w4.x; acc.y += xv * w4.y;
        acc.z += xv * w4.z; acc.w += xv * w4.w;
    }
    int gr = row0 + r;
    if (gr < n) *(float4*)&Y[gr * 64 + c4] = acc;
}

__global__ void gemm64_x_to_tmp(const float* __restrict__ X, const float* __restrict__ W, int n) {
    gemm64_body(X, W, d_tmp, n);
}
__global__ void gemm64_h_to_tmp(const float* __restrict__ W, int n) {
    gemm64_body(d_h, W, d_tmp, n);
}
__global__ void gemm64_h_to_B(const float* __restrict__ W, int n) {
    gemm64_body(d_h, W, d_B, n);
}

// ---------------- per-node attention dots (on d_tmp) ----------------
__global__ void node_dots_tmp(const float* __restrict__ attl, const float* __restrict__ attr_, int n) {
    int gw = (blockIdx.x * blockDim.x + threadIdx.x) >> 5;
    if (gw >= n) return;
    int lane = threadIdx.x & 31;
    float2 hv = ((const float2*)d_tmp)[gw * 32 + lane];
    float2 l2 = ((const float2*)attl)[lane];
    float2 r2 = ((const float2*)attr_)[lane];
    float pl = hv.x * l2.x + hv.y * l2.y;
    float pr = hv.x * r2.x + hv.y * r2.y;
    #pragma unroll
    for (int o = 16; o; o >>= 1) {
        pl += __shfl_xor_sync(~0u, pl, o);
        pr += __shfl_xor_sync(~0u, pr, o);
    }
    if (lane == 0) { d_al[gw] = pl; d_ar[gw] = pr; }
}

// ---------------- warp-per-node online-softmax aggregation (d_tmp -> d_h) ----------------
__global__ void aggregate_tmp_to_h(const float* __restrict__ bias, int n) {
    int gw = (blockIdx.x * blockDim.x + threadIdx.x) >> 5;
    if (gw >= n) return;
    int lane = threadIdx.x & 31;
    const float2* h2 = (const float2*)d_tmp;
    float2 hd = h2[gw * 32 + lane];
    float ar_i = d_ar[gw];
    float al_i = d_al[gw];

    // self loop
    float p = hd.x * hd.x + hd.y * hd.y;
    #pragma unroll
    for (int o = 16; o; o >>= 1) p += __shfl_xor_sync(~0u, p, o);
    float a = (al_i + ar_i) * __fdividef(1.f, 1.f + __expf(-p));
    a = fmaxf(a, 0.2f * a);  // leaky relu
    float m = a, s = 1.f;
    float2 acc = hd;

    int beg = d_rp[gw], end = d_rp[gw + 1];
    for (int k = beg; k < end; ++k) {
        int src = d_csr[k];
        float2 hs = h2[src * 32 + lane];
        float q = hd.x * hs.x + hd.y * hs.y;
        #pragma unroll
        for (int o = 16; o; o >>= 1) q += __shfl_xor_sync(~0u, q, o);
        float aa = (d_al[src] + ar_i) * __fdividef(1.f, 1.f + __expf(-q));
        aa = fmaxf(aa, 0.2f * aa);
        if (aa > m) {
            float cscale = __expf(m - aa);
            s = s * cscale + 1.f;
            acc.x = acc.x * cscale + hs.x;
            acc.y = acc.y * cscale + hs.y;
            m = aa;
        } else {
            float e = __expf(aa - m);
            s += e;
            acc.x += e * hs.x;
            acc.y += e * hs.y;
        }
    }
    float inv = __fdividef(1.f, s);
    float2 bv = ((const float2*)bias)[lane];
    float ox = fmaxf(acc.x * inv + bv.x, 0.f);
    float oy = fmaxf(acc.y * inv + bv.y, 0.f);
    ((float2*)d_h)[gw * 32 + lane] = make_float2(ox, oy);
}

// ---------------- edge MLP: relu(A[src]+B[dst]+attr*we+bm1) @ Wm2 + bm2 ----------------
__global__ void edge_mlp(const int* __restrict__ ei, const float* __restrict__ eattr,
                         const float* __restrict__ Wm1, const float* __restrict__ bm1,
                         const float* __restrict__ Wm2, const float* __restrict__ bm2,
                         float* __restrict__ out, int E) {
    __shared__ float swe[64], sb[64], sw2[64];
    int tid = threadIdx.x;
    if (tid < 64) {
        swe[tid] = Wm1[64 * 64 + tid];  // row 64 of [129,64]
        sb[tid]  = bm1[tid];
        sw2[tid] = Wm2[tid];
    }
    __syncthreads();
    int gw = (blockIdx.x * blockDim.x + tid) >> 5;
    if (gw >= E) return;
    int lane = tid & 31;
    int src = ei[gw];
    int dst = ei[E + gw];
    float at = eattr[gw];
    float2 a2 = ((const float2*)d_tmp)[src * 32 + lane];
    float2 b2 = ((const float2*)d_B)[dst * 32 + lane];
    float2 we = ((const float2*)swe)[lane];
    float2 bb = ((const float2*)sb)[lane];
    float2 w2 = ((const float2*)sw2)[lane];
    float vx = fmaxf(a2.x + b2.x + at * we.x + bb.x, 0.f);
    float vy = fmaxf(a2.y + b2.y + at * we.y + bb.y, 0.f);
    float p = vx * w2.x + vy * w2.y;
    #pragma unroll
    for (int o = 16; o; o >>= 1) p += __shfl_xor_sync(~0u, p, o);
    if (lane == 0) out[gw] = p + bm2[0];
}

// ---------------- launch ----------------
extern "C" void kernel_launch(void* const* d_in, const int* in_sizes, int n_in,
                              void* d_out, int out_size) {
    const float* x     = (const float*)d_in[0];
    const int*   ei    = (const int*)d_in[1];     // int32: JAX x64 disabled
    const float* eattr = (const float*)d_in[2];
    const float* W1    = (const float*)d_in[3];
    const float* attl1 = (const float*)d_in[4];
    const float* attr1 = (const float*)d_in[5];
    const float* b1    = (const float*)d_in[6];
    const float* W2    = (const float*)d_in[7];
    const float* attl2 = (const float*)d_in[8];
    const float* attr2 = (const float*)d_in[9];
    const float* b2    = (const float*)d_in[10];
    const float* Wm1   = (const float*)d_in[11];
    const float* bm1   = (const float*)d_in[12];
    const float* Wm2   = (const float*)d_in[13];
    const float* bm2   = (const float*)d_in[14];
    float* out = (float*)d_out;

    int N = in_sizes[0] / C;
    int E = in_sizes[2];  // edge_attr has E elements (EDGE_D = 1)

    int eb = (E + 255) / 256;
    int nb_warp = (N * 32 + 255) / 256;
    int gb = (N + 15) / 16;

    // CSR build (dst-grouped)
    zero_k<<<(N + 255) / 256, 256>>>(N);
    count_k<<<eb, 256>>>(ei, E);
    scan_k<<<1, 1024>>>(N);
    scatter_k<<<eb, 256>>>(ei, E);

    // layer 1
    gemm64_x_to_tmp<<<gb, 256>>>(x, W1, N);
    node_dots_tmp<<<nb_warp, 256>>>(attl1, attr1, N);
    aggregate_tmp_to_h<<<nb_warp, 256>>>(b1, N);

    // layer 2
    gemm64_h_to_tmp<<<gb, 256>>>(W2, N);
    node_dots_tmp<<<nb_warp, 256>>>(attl2, attr2, N);
    aggregate_tmp_to_h<<<nb_warp, 256>>>(b2, N);

    // edge MLP: A = h @ Wm1[0:64] -> d_tmp, B = h @ Wm1[65:129] -> d_B
    gemm64_h_to_tmp<<<gb, 256>>>(Wm1, N);
    gemm64_h_to_B<<<gb, 256>>>(Wm1 + 65 * 64, N);
    edge_mlp<<<(E * 32 + 255) / 256, 256>>>(ei, eattr, Wm1, bm1, Wm2, bm2, out, E);
}

// round 4
// speedup vs baseline: 1.2179x; 1.2179x over previous
#include <cuda_runtime.h>
#include <cuda_bf16.h>

#define MAXN 50000
#define MAXE 1000000
#define C 64

// ---------------- device scratch (no allocations allowed) ----------------
__device__ __align__(16) float d_tmp[MAXN * C];   // pre-agg h (x@W); reused as A in MLP stage
__device__ __align__(16) float d_h[MAXN * C];     // layer output (relu'd)
__device__ __align__(16) float d_B[MAXN * C];     // h@Wm1_bot
__device__ float d_al[MAXN];
__device__ float d_ar[MAXN];
__device__ int   d_cnt[MAXN];
__device__ int   d_cur[MAXN];
__device__ int   d_rp[MAXN + 1];
__device__ int   d_csr[MAXE];
__device__ int   d_eid[MAXE];

// ---------------- CSR build ----------------
__global__ void zero_k(int n) {
    int i = blockIdx.x * blockDim.x + threadIdx.x;
    if (i < n) d_cnt[i] = 0;
}

__global__ void count_k(const int* __restrict__ ei, int E) {
    int e = blockIdx.x * blockDim.x + threadIdx.x;
    if (e < E) atomicAdd(&d_cnt[ei[E + e]], 1);
}

// single-block scan over up to MAXN counts
__global__ void scan_k(int n) {
    __shared__ int warpsum[32];
    __shared__ int s_carry;
    int tid = threadIdx.x, lane = tid & 31, w = tid >> 5;
    if (tid == 0) s_carry = 0;
    __syncthreads();
    for (int base = 0; base < n; base += 1024) {
        int i = base + tid;
        int v = (i < n) ? d_cnt[i] : 0;
        int x = v;
        #pragma unroll
        for (int o = 1; o < 32; o <<= 1) {
            int t = __shfl_up_sync(~0u, x, o);
            if (lane >= o) x += t;
        }
        if (lane == 31) warpsum[w] = x;
        __syncthreads();
        if (w == 0) {
            int y = warpsum[lane];
            #pragma unroll
            for (int o = 1; o < 32; o <<= 1) {
                int t = __shfl_up_sync(~0u, y, o);
                if (lane >= o) y += t;
            }
            warpsum[lane] = y;
        }
        __syncthreads();
        int incl = x + (w > 0 ? warpsum[w - 1] : 0) + s_carry;
        if (i < n) { d_rp[i] = incl - v; d_cur[i] = incl - v; }
        __syncthreads();
        if (tid == 1023) s_carry = incl;
        __syncthreads();
    }
    if (threadIdx.x == 0) d_rp[n] = s_carry;
}

__global__ void scatter_k(const int* __restrict__ ei, int E) {
    int e = blockIdx.x * blockDim.x + threadIdx.x;
    if (e < E) {
        int src = ei[e];
        int dst = ei[E + e];
        int pos = atomicAdd(&d_cur[dst], 1);
        d_csr[pos] = src;
        d_eid[pos] = e;
    }
}

// ---------------- GEMM: Y[n x 64] = X[n x 64] @ W[64 x 64] ----------------
__device__ __forceinline__ void gemm64_body(const float* __restrict__ X,
                                            const float* __restrict__ W,
                                            float* __restrict__ Y, int n) {
    __shared__ float sW[64 * 64];
    __shared__ float sX[16 * 64];
    int tid = threadIdx.x;  // 256
    int row0 = blockIdx.x * 16;
    #pragma unroll
    for (int i = 0; i < 16; i++) sW[tid + 256 * i] = W[tid + 256 * i];
    #pragma unroll
    for (int i = 0; i < 4; i++) {
        int idx = tid + 256 * i;
        int r = idx >> 6, c = idx & 63;
        int gr = row0 + r;
        sX[idx] = (gr < n) ? X[gr * 64 + c] : 0.f;
    }
    __syncthreads();
    int r = tid >> 4;
    int c4 = (tid & 15) * 4;
    float4 acc = {0.f, 0.f, 0.f, 0.f};
    #pragma unroll
    for (int k = 0; k < 64; k++) {
        float xv = sX[r * 64 + k];
        float4 w4 = *(const float4*)&sW[k * 64 + c4];
        acc.x += xv * w4.x; acc.y += xv * w4.y;
        acc.z += xv * w4.z; acc.w += xv * w4.w;
    }
    int gr = row0 + r;
    if (gr < n) *(float4*)&Y[gr * 64 + c4] = acc;
}

__global__ void gemm64_x_to_tmp(const float* __restrict__ X, const float* __restrict__ W, int n) {
    gemm64_body(X, W, d_tmp, n);
}
__global__ void gemm64_h_to_tmp(const float* __restrict__ W, int n) {
    gemm64_body(d_h, W, d_tmp, n);
}

// fused: A = h@W_top -> d_tmp, B = h@W_bot -> d_B (h loaded once)
__global__ void gemm64_mlp2(const float* __restrict__ Wtop, const float* __restrict__ Wbot, int n) {
    __shared__ float sW1[64 * 64];
    __shared__ float sW2[64 * 64];
    __shared__ float sX[16 * 64];
    int tid = threadIdx.x;  // 256
    int row0 = blockIdx.x * 16;
    #pragma unroll
    for (int i = 0; i < 16; i++) {
        sW1[tid + 256 * i] = Wtop[tid + 256 * i];
        sW2[tid + 256 * i] = Wbot[tid + 256 * i];
    }
    #pragma unroll
    for (int i = 0; i < 4; i++) {
        int idx = tid + 256 * i;
        int r = idx >> 6, c = idx & 63;
        int gr = row0 + r;
        sX[idx] = (gr < n) ? d_h[gr * 64 + c] : 0.f;
    }
    __syncthreads();
    int r = tid >> 4;
    int c4 = (tid & 15) * 4;
    float4 a = {0.f, 0.f, 0.f, 0.f};
    float4 b = {0.f, 0.f, 0.f, 0.f};
    #pragma unroll
    for (int k = 0; k < 64; k++) {
        float xv = sX[r * 64 + k];
        float4 w1 = *(const float4*)&sW1[k * 64 + c4];
        float4 w2 = *(const float4*)&sW2[k * 64 + c4];
        a.x += xv * w1.x; a.y += xv * w1.y; a.z += xv * w1.z; a.w += xv * w1.w;
        b.x += xv * w2.x; b.y += xv * w2.y; b.z += xv * w2.z; b.w += xv * w2.w;
    }
    int gr = row0 + r;
    if (gr < n) {
        *(float4*)&d_tmp[gr * 64 + c4] = a;
        *(float4*)&d_B[gr * 64 + c4] = b;
    }
}

// ---------------- per-node attention dots (on d_tmp) ----------------
__global__ void node_dots_tmp(const float* __restrict__ attl, const float* __restrict__ attr_, int n) {
    int gw = (blockIdx.x * blockDim.x + threadIdx.x) >> 5;
    if (gw >= n) return;
    int lane = threadIdx.x & 31;
    float2 hv = ((const float2*)d_tmp)[gw * 32 + lane];
    float2 l2 = ((const float2*)attl)[lane];
    float2 r2 = ((const float2*)attr_)[lane];
    float pl = hv.x * l2.x + hv.y * l2.y;
    float pr = hv.x * r2.x + hv.y * r2.y;
    #pragma unroll
    for (int o = 16; o; o >>= 1) {
        pl += __shfl_xor_sync(~0u, pl, o);
        pr += __shfl_xor_sync(~0u, pr, o);
    }
    if (lane == 0) { d_al[gw] = pl; d_ar[gw] = pr; }
}

__device__ __forceinline__ float lrelu_sig(float base, float q) {
    float a = base * __fdividef(1.f, 1.f + __expf(-q));
    return fmaxf(a, 0.2f * a);
}

// ---------------- warp-per-node online-softmax aggregation (d_tmp -> d_h) ----------------
// 4 edges per iteration, interleaved butterflies, branchless online-softmax update.
__global__ void aggregate_tmp_to_h(const float* __restrict__ bias, int n) {
    int gw = (blockIdx.x * blockDim.x + threadIdx.x) >> 5;
    if (gw >= n) return;
    int lane = threadIdx.x & 31;
    const float2* h2 = (const float2*)d_tmp;
    float2 hd = h2[gw * 32 + lane];
    float ar_i = d_ar[gw];
    float al_i = d_al[gw];

    // self loop
    float p = hd.x * hd.x + hd.y * hd.y;
    #pragma unroll
    for (int o = 16; o; o >>= 1) p += __shfl_xor_sync(~0u, p, o);
    float m = lrelu_sig(al_i + ar_i, p);
    float s = 1.f;
    float2 acc = hd;

    int beg = d_rp[gw], end = d_rp[gw + 1];
    for (int k = beg; k < end; k += 4) {
        int cnt = end - k;
        int s0 = d_csr[k];
        int s1 = (cnt > 1) ? d_csr[k + 1] : s0;
        int s2 = (cnt > 2) ? d_csr[k + 2] : s0;
        int s3 = (cnt > 3) ? d_csr[k + 3] : s0;
        float2 v0 = h2[s0 * 32 + lane];
        float2 v1 = h2[s1 * 32 + lane];
        float2 v2 = h2[s2 * 32 + lane];
        float2 v3 = h2[s3 * 32 + lane];
        float q0 = hd.x * v0.x + hd.y * v0.y;
        float q1 = hd.x * v1.x + hd.y * v1.y;
        float q2 = hd.x * v2.x + hd.y * v2.y;
        float q3 = hd.x * v3.x + hd.y * v3.y;
        #pragma unroll
        for (int o = 16; o; o >>= 1) {
            q0 += __shfl_xor_sync(~0u, q0, o);
            q1 += __shfl_xor_sync(~0u, q1, o);
            q2 += __shfl_xor_sync(~0u, q2, o);
            q3 += __shfl_xor_sync(~0u, q3, o);
        }
        float a0 = lrelu_sig(d_al[s0] + ar_i, q0);
        float a1 = (cnt > 1) ? lrelu_sig(d_al[s1] + ar_i, q1) : -1e30f;
        float a2 = (cnt > 2) ? lrelu_sig(d_al[s2] + ar_i, q2) : -1e30f;
        float a3 = (cnt > 3) ? lrelu_sig(d_al[s3] + ar_i, q3) : -1e30f;

        float nm = fmaxf(m, fmaxf(fmaxf(a0, a1), fmaxf(a2, a3)));
        float cs = __expf(m - nm);
        float e0 = __expf(a0 - nm);
        float e1 = __expf(a1 - nm);
        float e2 = __expf(a2 - nm);
        float e3 = __expf(a3 - nm);
        s = s * cs + e0 + e1 + e2 + e3;
        acc.x = acc.x * cs + e0 * v0.x + e1 * v1.x + e2 * v2.x + e3 * v3.x;
        acc.y = acc.y * cs + e0 * v0.y + e1 * v1.y + e2 * v2.y + e3 * v3.y;
        m = nm;
    }
    float inv = __fdividef(1.f, s);
    float2 bv = ((const float2*)bias)[lane];
    float ox = fmaxf(acc.x * inv + bv.x, 0.f);
    float oy = fmaxf(acc.y * inv + bv.y, 0.f);
    ((float2*)d_h)[gw * 32 + lane] = make_float2(ox, oy);
}

// ---------------- edge MLP, CSR-grouped: warp per dst node ----------------
// out[eid] = relu(A[src] + B[dst] + attr*we + bm1) @ Wm2 + bm2
__global__ void edge_mlp_csr(const float* __restrict__ eattr,
                             const float* __restrict__ Wm1, const float* __restrict__ bm1,
                             const float* __restrict__ Wm2, const float* __restrict__ bm2,
                             float* __restrict__ out, int n) {
    int gw = (blockIdx.x * blockDim.x + threadIdx.x) >> 5;
    if (gw >= n) return;
    int lane = threadIdx.x & 31;
    float2 we = ((const float2*)(Wm1 + 64 * 64))[lane];  // row 64 of [129,64]
    float2 bb = ((const float2*)bm1)[lane];
    float2 w2 = ((const float2*)Wm2)[lane];
    float b2c = bm2[0];
    float2 bd = ((const float2*)d_B)[gw * 32 + lane];
    bd.x += bb.x; bd.y += bb.y;  // fold bm1 into dst term
    const float2* A2 = (const float2*)d_tmp;

    int beg = d_rp[gw], end = d_rp[gw + 1];
    for (int k = beg; k < end; k += 4) {
        int cnt = end - k;
        int s0 = d_csr[k];
        int s1 = (cnt > 1) ? d_csr[k + 1] : s0;
        int s2 = (cnt > 2) ? d_csr[k + 2] : s0;
        int s3 = (cnt > 3) ? d_csr[k + 3] : s0;
        int e0 = d_eid[k];
        int e1 = (cnt > 1) ? d_eid[k + 1] : e0;
        int e2 = (cnt > 2) ? d_eid[k + 2] : e0;
        int e3 = (cnt > 3) ? d_eid[k + 3] : e0;
        float t0 = eattr[e0], t1 = eattr[e1], t2 = eattr[e2], t3 = eattr[e3];
        float2 a0 = A2[s0 * 32 + lane];
        float2 a1 = A2[s1 * 32 + lane];
        float2 a2 = A2[s2 * 32 + lane];
        float2 a3 = A2[s3 * 32 + lane];
        float vx, vy;
        vx = fmaxf(a0.x + bd.x + t0 * we.x, 0.f);
        vy = fmaxf(a0.y + bd.y + t0 * we.y, 0.f);
        float p0 = vx * w2.x + vy * w2.y;
        vx = fmaxf(a1.x + bd.x + t1 * we.x, 0.f);
        vy = fmaxf(a1.y + bd.y + t1 * we.y, 0.f);
        float p1 = vx * w2.x + vy * w2.y;
        vx = fmaxf(a2.x + bd.x + t2 * we.x, 0.f);
        vy = fmaxf(a2.y + bd.y + t2 * we.y, 0.f);
        float p2 = vx * w2.x + vy * w2.y;
        vx = fmaxf(a3.x + bd.x + t3 * we.x, 0.f);
        vy = fmaxf(a3.y + bd.y + t3 * we.y, 0.f);
        float p3 = vx * w2.x + vy * w2.y;
        #pragma unroll
        for (int o = 16; o; o >>= 1) {
            p0 += __shfl_xor_sync(~0u, p0, o);
            p1 += __shfl_xor_sync(~0u, p1, o);
            p2 += __shfl_xor_sync(~0u, p2, o);
            p3 += __shfl_xor_sync(~0u, p3, o);
        }
        if (lane == 0) {
            out[e0] = p0 + b2c;
            if (cnt > 1) out[e1] = p1 + b2c;
            if (cnt > 2) out[e2] = p2 + b2c;
            if (cnt > 3) out[e3] = p3 + b2c;
        }
    }
}

// ---------------- launch ----------------
extern "C" void kernel_launch(void* const* d_in, const int* in_sizes, int n_in,
                              void* d_out, int out_size) {
    const float* x     = (const float*)d_in[0];
    const int*   ei    = (const int*)d_in[1];     // int32: JAX x64 disabled
    const float* eattr = (const float*)d_in[2];
    const float* W1    = (const float*)d_in[3];
    const float* attl1 = (const float*)d_in[4];
    const float* attr1 = (const float*)d_in[5];
    const float* b1    = (const float*)d_in[6];
    const float* W2    = (const float*)d_in[7];
    const float* attl2 = (const float*)d_in[8];
    const float* attr2 = (const float*)d_in[9];
    const float* b2    = (const float*)d_in[10];
    const float* Wm1   = (const float*)d_in[11];
    const float* bm1   = (const float*)d_in[12];
    const float* Wm2   = (const float*)d_in[13];
    const float* bm2   = (const float*)d_in[14];
    float* out = (float*)d_out;

    int N = in_sizes[0] / C;
    int E = in_sizes[2];  // edge_attr has E elements (EDGE_D = 1)

    int eb = (E + 255) / 256;
    int nb_warp = (N * 32 + 255) / 256;
    int gb = (N + 15) / 16;

    // CSR build (dst-grouped, with edge ids)
    zero_k<<<(N + 255) / 256, 256>>>(N);
    count_k<<<eb, 256>>>(ei, E);
    scan_k<<<1, 1024>>>(N);
    scatter_k<<<eb, 256>>>(ei, E);

    // layer 1
    gemm64_x_to_tmp<<<gb, 256>>>(x, W1, N);
    node_dots_tmp<<<nb_warp, 256>>>(attl1, attr1, N);
    aggregate_tmp_to_h<<<nb_warp, 256>>>(b1, N);

    // layer 2
    gemm64_h_to_tmp<<<gb, 256>>>(W2, N);
    node_dots_tmp<<<nb_warp, 256>>>(attl2, attr2, N);
    aggregate_tmp_to_h<<<nb_warp, 256>>>(b2, N);

    // edge MLP: A = h @ Wm1[0:64] -> d_tmp, B = h @ Wm1[65:129] -> d_B (fused)
    gemm64_mlp2<<<gb, 256>>>(Wm1, Wm1 + 65 * 64, N);
    edge_mlp_csr<<<nb_warp, 256>>>(eattr, Wm1, bm1, Wm2, bm2, out, N);
}

// round 5
// speedup vs baseline: 1.3389x; 1.0993x over previous
#include <cuda_runtime.h>
#include <cuda_bf16.h>

#define MAXN 50000
#define MAXE 1000000
#define C 64

// ---------------- device scratch ----------------
__device__ __align__(16) float d_tmp[MAXN * C];   // pre-agg h; reused as A in MLP stage
__device__ __align__(16) float d_h[MAXN * C];     // layer output (relu'd)
__device__ __align__(16) float d_B[MAXN * C];     // h@Wm1_bot
__device__ float d_al[MAXN];
__device__ float d_ar[MAXN];
__device__ float d_eatt[MAXE];
__device__ int   d_cnt[MAXN];
__device__ int   d_cur[MAXN];
__device__ int   d_rp[MAXN + 1];
__device__ int   d_csr[MAXE];
__device__ int   d_eid[MAXE];
__device__ int   d_bsum[65];

// ---------------- CSR build ----------------
__global__ void zero_k(int n) {
    int i = blockIdx.x * blockDim.x + threadIdx.x;
    if (i < n) d_cnt[i] = 0;
}

__global__ void count_k(const int* __restrict__ ei, int E) {
    int e = blockIdx.x * blockDim.x + threadIdx.x;
    if (e < E) atomicAdd(&d_cnt[ei[E + e]], 1);
}

// block-local exclusive scan (1024/block); block totals to d_bsum
__global__ void scan_local(int n) {
    __shared__ int wsum[32];
    int tid = threadIdx.x, lane = tid & 31, w = tid >> 5;
    int i = blockIdx.x * 1024 + tid;
    int v = (i < n) ? d_cnt[i] : 0;
    int x = v;
    #pragma unroll
    for (int o = 1; o < 32; o <<= 1) {
        int t = __shfl_up_sync(~0u, x, o);
        if (lane >= o) x += t;
    }
    if (lane == 31) wsum[w] = x;
    __syncthreads();
    if (w == 0) {
        int y = wsum[lane];
        #pragma unroll
        for (int o = 1; o < 32; o <<= 1) {
            int t = __shfl_up_sync(~0u, y, o);
            if (lane >= o) y += t;
        }
        wsum[lane] = y;
    }
    __syncthreads();
    int incl = x + (w > 0 ? wsum[w - 1] : 0);
    if (i < n) d_rp[i] = incl - v;
    if (tid == 1023) d_bsum[blockIdx.x] = incl;
}

// scan the (<=64) block sums; total -> d_bsum[64]
__global__ void scan_bsums(int nb) {
    __shared__ int ws[2];
    int t = threadIdx.x, lane = t & 31, w = t >> 5;
    int v = (t < nb) ? d_bsum[t] : 0;
    int x = v;
    #pragma unroll
    for (int o = 1; o < 32; o <<= 1) {
        int tt = __shfl_up_sync(~0u, x, o);
        if (lane >= o) x += tt;
    }
    if (lane == 31) ws[w] = x;
    __syncthreads();
    if (w == 1) x += ws[0];
    d_bsum[t] = x - v;
    if (t == 63) d_bsum[64] = x;
}

__global__ void scan_add(int n) {
    int i = blockIdx.x * blockDim.x + threadIdx.x;
    if (i < n) {
        int val = d_rp[i] + d_bsum[i >> 10];
        d_rp[i] = val;
        d_cur[i] = val;
    }
    if (i == 0) d_rp[n] = d_bsum[64];
}

__global__ void scatter_k(const int* __restrict__ ei, const float* __restrict__ eattr, int E) {
    int e = blockIdx.x * blockDim.x + threadIdx.x;
    if (e < E) {
        int src = ei[e];
        int dst = ei[E + e];
        int pos = atomicAdd(&d_cur[dst], 1);
        d_csr[pos] = src;
        d_eid[pos] = e;
        d_eatt[pos] = eattr[e];
    }
}

// ---------------- GEMM + fused attention dots: d_tmp = X@W, d_al/d_ar ----------------
__device__ __forceinline__ void gemm64_att_body(const float* __restrict__ X,
                                                const float* __restrict__ W,
                                                const float* __restrict__ attl,
                                                const float* __restrict__ attr_, int n) {
    __shared__ float sW[64 * 64];
    __shared__ float sX[16 * 64];
    int tid = threadIdx.x;  // 256
    int row0 = blockIdx.x * 16;
    #pragma unroll
    for (int i = 0; i < 16; i++) sW[tid + 256 * i] = W[tid + 256 * i];
    #pragma unroll
    for (int i = 0; i < 4; i++) {
        int idx = tid + 256 * i;
        int r = idx >> 6, c = idx & 63;
        int gr = row0 + r;
        sX[idx] = (gr < n) ? X[gr * 64 + c] : 0.f;
    }
    __syncthreads();
    int r = tid >> 4;
    int c4 = (tid & 15) * 4;
    float4 acc = {0.f, 0.f, 0.f, 0.f};
    #pragma unroll
    for (int k = 0; k < 64; k++) {
        float xv = sX[r * 64 + k];
        float4 w4 = *(const float4*)&sW[k * 64 + c4];
        acc.x += xv * w4.x; acc.y += xv * w4.y;
        acc.z += xv * w4.z; acc.w += xv * w4.w;
    }
    float4 l4 = *(const float4*)&attl[c4];
    float4 r4 = *(const float4*)&attr_[c4];
    float la = acc.x * l4.x + acc.y * l4.y + acc.z * l4.z + acc.w * l4.w;
    float ra = acc.x * r4.x + acc.y * r4.y + acc.z * r4.z + acc.w * r4.w;
    #pragma unroll
    for (int o = 8; o; o >>= 1) {
        la += __shfl_xor_sync(~0u, la, o);
        ra += __shfl_xor_sync(~0u, ra, o);
    }
    int gr = row0 + r;
    if (gr < n) {
        *(float4*)&d_tmp[gr * 64 + c4] = acc;
        if ((tid & 15) == 0) { d_al[gr] = la; d_ar[gr] = ra; }
    }
}

__global__ void gemm64_att_x(const float* __restrict__ X, const float* __restrict__ W,
                             const float* __restrict__ attl, const float* __restrict__ attr_, int n) {
    gemm64_att_body(X, W, attl, attr_, n);
}
__global__ void gemm64_att_h(const float* __restrict__ W,
                             const float* __restrict__ attl, const float* __restrict__ attr_, int n) {
    gemm64_att_body(d_h, W, attl, attr_, n);
}

// fused: A = h@W_top -> d_tmp, B = h@W_bot -> d_B
__global__ void gemm64_mlp2(const float* __restrict__ Wtop, const float* __restrict__ Wbot, int n) {
    __shared__ float sW1[64 * 64];
    __shared__ float sW2[64 * 64];
    __shared__ float sX[16 * 64];
    int tid = threadIdx.x;
    int row0 = blockIdx.x * 16;
    #pragma unroll
    for (int i = 0; i < 16; i++) {
        sW1[tid + 256 * i] = Wtop[tid + 256 * i];
        sW2[tid + 256 * i] = Wbot[tid + 256 * i];
    }
    #pragma unroll
    for (int i = 0; i < 4; i++) {
        int idx = tid + 256 * i;
        int r = idx >> 6, c = idx & 63;
        int gr = row0 + r;
        sX[idx] = (gr < n) ? d_h[gr * 64 + c] : 0.f;
    }
    __syncthreads();
    int r = tid >> 4;
    int c4 = (tid & 15) * 4;
    float4 a = {0.f, 0.f, 0.f, 0.f};
    float4 b = {0.f, 0.f, 0.f, 0.f};
    #pragma unroll
    for (int k = 0; k < 64; k++) {
        float xv = sX[r * 64 + k];
        float4 w1 = *(const float4*)&sW1[k * 64 + c4];
        float4 w2 = *(const float4*)&sW2[k * 64 + c4];
        a.x += xv * w1.x; a.y += xv * w1.y; a.z += xv * w1.z; a.w += xv * w1.w;
        b.x += xv * w2.x; b.y += xv * w2.y; b.z += xv * w2.z; b.w += xv * w2.w;
    }
    int gr = row0 + r;
    if (gr < n) {
        *(float4*)&d_tmp[gr * 64 + c4] = a;
        *(float4*)&d_B[gr * 64 + c4] = b;
    }
}

__device__ __forceinline__ float lrelu_sig(float base, float q) {
    float a = base * __fdividef(1.f, 1.f + __expf(-q));
    return fmaxf(a, 0.2f * a);
}

// ---------------- half-warp (16-lane x float4) online-softmax aggregation ----------------
// warp handles 2 nodes; 8 edges per iteration, interleaved 4-stage butterflies.
__global__ void aggregate2(const float* __restrict__ bias, int n) {
    int gw = (blockIdx.x * blockDim.x + threadIdx.x) >> 5;
    int lane = threadIdx.x & 31;
    int half = lane >> 4, l = lane & 15;
    int node = gw * 2 + half;
    if (node >= n) return;
    unsigned mk = 0xFFFFu << (half * 16);
    const float4* h4 = (const float4*)d_tmp;
    float4 hd = h4[node * 16 + l];
    float ar_i = d_ar[node];
    float al_i = d_al[node];

    // self loop
    float p = hd.x * hd.x + hd.y * hd.y + hd.z * hd.z + hd.w * hd.w;
    #pragma unroll
    for (int o = 8; o; o >>= 1) p += __shfl_xor_sync(mk, p, o);
    float m = lrelu_sig(al_i + ar_i, p);
    float s = 1.f;
    float4 acc = hd;

    int beg = d_rp[node], end = d_rp[node + 1];
    for (int k = beg; k < end; k += 8) {
        int id[8];
        float4 v[8];
        float q[8];
        #pragma unroll
        for (int i = 0; i < 8; i++) id[i] = (k + i < end) ? d_csr[k + i] : d_csr[k];
        #pragma unroll
        for (int i = 0; i < 8; i++) v[i] = h4[id[i] * 16 + l];
        #pragma unroll
        for (int i = 0; i < 8; i++)
            q[i] = hd.x * v[i].x + hd.y * v[i].y + hd.z * v[i].z + hd.w * v[i].w;
        #pragma unroll
        for (int o = 8; o; o >>= 1) {
            #pragma unroll
            for (int i = 0; i < 8; i++) q[i] += __shfl_xor_sync(mk, q[i], o);
        }
        float a[8];
        #pragma unroll
        for (int i = 0; i < 8; i++)
            a[i] = (k + i < end) ? lrelu_sig(d_al[id[i]] + ar_i, q[i]) : -1e30f;
        float nm = m;
        #pragma unroll
        for (int i = 0; i < 8; i++) nm = fmaxf(nm, a[i]);
        float cs = __expf(m - nm);
        s *= cs;
        acc.x *= cs; acc.y *= cs; acc.z *= cs; acc.w *= cs;
        #pragma unroll
        for (int i = 0; i < 8; i++) {
            float e = __expf(a[i] - nm);
            s += e;
            acc.x += e * v[i].x; acc.y += e * v[i].y;
            acc.z += e * v[i].z; acc.w += e * v[i].w;
        }
        m = nm;
    }
    float inv = __fdividef(1.f, s);
    float4 bv = ((const float4*)bias)[l];
    float4 o;
    o.x = fmaxf(acc.x * inv + bv.x, 0.f);
    o.y = fmaxf(acc.y * inv + bv.y, 0.f);
    o.z = fmaxf(acc.z * inv + bv.z, 0.f);
    o.w = fmaxf(acc.w * inv + bv.w, 0.f);
    ((float4*)d_h)[node * 16 + l] = o;
}

// ---------------- edge MLP, CSR-grouped, half-warp, batch 8 ----------------
__global__ void edge_mlp2(const float* __restrict__ Wm1, const float* __restrict__ bm1,
                          const float* __restrict__ Wm2, const float* __restrict__ bm2,
                          float* __restrict__ out, int n) {
    int gw = (blockIdx.x * blockDim.x + threadIdx.x) >> 5;
    int lane = threadIdx.x & 31;
    int half = lane >> 4, l = lane & 15;
    int node = gw * 2 + half;
    if (node >= n) return;
    unsigned mk = 0xFFFFu << (half * 16);
    float4 we = ((const float4*)(Wm1 + 64 * 64))[l];  // row 64 of [129,64]
    float4 bb = ((const float4*)bm1)[l];
    float4 w2 = ((const float4*)Wm2)[l];
    float b2c = bm2[0];
    float4 bd = ((const float4*)d_B)[node * 16 + l];
    bd.x += bb.x; bd.y += bb.y; bd.z += bb.z; bd.w += bb.w;
    const float4* A4 = (const float4*)d_tmp;

    int beg = d_rp[node], end = d_rp[node + 1];
    for (int k = beg; k < end; k += 8) {
        int id[8], eo[8];
        float t[8], p[8];
        #pragma unroll
        for (int i = 0; i < 8; i++) {
            bool ok = (k + i < end);
            id[i] = ok ? d_csr[k + i] : d_csr[k];
            eo[i] = ok ? d_eid[k + i] : -1;
            t[i]  = ok ? d_eatt[k + i] : 0.f;
        }
        #pragma unroll
        for (int i = 0; i < 8; i++) {
            float4 a = A4[id[i] * 16 + l];
            float vx = fmaxf(a.x + bd.x + t[i] * we.x, 0.f);
            float vy = fmaxf(a.y + bd.y + t[i] * we.y, 0.f);
            float vz = fmaxf(a.z + bd.z + t[i] * we.z, 0.f);
            float vw = fmaxf(a.w + bd.w + t[i] * we.w, 0.f);
            p[i] = vx * w2.x + vy * w2.y + vz * w2.z + vw * w2.w;
        }
        #pragma unroll
        for (int o = 8; o; o >>= 1) {
            #pragma unroll
            for (int i = 0; i < 8; i++) p[i] += __shfl_xor_sync(mk, p[i], o);
        }
        if (l == 0) {
            #pragma unroll
            for (int i = 0; i < 8; i++)
                if (eo[i] >= 0) out[eo[i]] = p[i] + b2c;
        }
    }
}

// ---------------- launch ----------------
extern "C" void kernel_launch(void* const* d_in, const int* in_sizes, int n_in,
                              void* d_out, int out_size) {
    const float* x     = (const float*)d_in[0];
    const int*   ei    = (const int*)d_in[1];     // int32: JAX x64 disabled
    const float* eattr = (const float*)d_in[2];
    const float* W1    = (const float*)d_in[3];
    const float* attl1 = (const float*)d_in[4];
    const float* attr1 = (const float*)d_in[5];
    const float* b1    = (const float*)d_in[6];
    const float* W2    = (const float*)d_in[7];
    const float* attl2 = (const float*)d_in[8];
    const float* attr2 = (const float*)d_in[9];
    const float* b2    = (const float*)d_in[10];
    const float* Wm1   = (const float*)d_in[11];
    const float* bm1   = (const float*)d_in[12];
    const float* Wm2   = (const float*)d_in[13];
    const float* bm2   = (const float*)d_in[14];
    float* out = (float*)d_out;

    int N = in_sizes[0] / C;
    int E = in_sizes[2];

    int eb = (E + 255) / 256;
    int gb = (N + 15) / 16;
    int npairs = (N + 1) / 2;
    int pb = (npairs * 32 + 255) / 256;
    int sb = (N + 1023) / 1024;

    // CSR build (dst-grouped, with edge ids + reordered attrs)
    zero_k<<<(N + 255) / 256, 256>>>(N);
    count_k<<<eb, 256>>>(ei, E);
    scan_local<<<sb, 1024>>>(N);
    scan_bsums<<<1, 64>>>(sb);
    scan_add<<<(N + 255) / 256, 256>>>(N);
    scatter_k<<<eb, 256>>>(ei, eattr, E);

    // layer 1 (GEMM with fused att dots)
    gemm64_att_x<<<gb, 256>>>(x, W1, attl1, attr1, N);
    aggregate2<<<pb, 256>>>(b1, N);

    // layer 2
    gemm64_att_h<<<gb, 256>>>(W2, attl2, attr2, N);
    aggregate2<<<pb, 256>>>(b2, N);

    // edge MLP
    gemm64_mlp2<<<gb, 256>>>(Wm1, Wm1 + 65 * 64, N);
    edge_mlp2<<<pb, 256>>>(Wm1, bm1, Wm2, bm2, out, N);
}